// round 16
// baseline (speedup 1.0000x reference)
#include <cuda_runtime.h>
#include <cuda_fp16.h>

#define NN 10000
#define EE 320000
#define ET (EE + NN)
#define F1 512    // HEADS*HID
#define HID 64
#define HEADS 8
#define PAD 32    // 128B stride for atomic counters (LTS spread)
#define BUCKET 128 // fixed per-node edge capacity (max deg ~57 « 128)

// ---------------- scratch (static device memory; no allocations) -------------
__device__ __half g_h1h[NN * F1];    // fp16 h1 (written by mma1 epilogue)
__device__ float  g_h1e[NN * F1];    // layer-1 output after bias+ELU
__device__ float  g_h2[NN * HID];    // h1e @ W2
__device__ float  g_es1[NN * HEADS];
__device__ float  g_ed1[NN * HEADS];
__device__ float  g_es2[NN];
__device__ float  g_ed2[NN];
__device__ int    g_cnt[NN * PAD];   // per-node degree counters (zero-init; self-cleaned by k_gat2)
__device__ int    g_csrc[NN * BUCKET];

__device__ __forceinline__ float lrelu(float e) { return e > 0.f ? e : 0.2f * e; }

__device__ __forceinline__ unsigned f2tf32(float f) {
    unsigned u;
    asm("cvt.rna.tf32.f32 %0, %1;" : "=r"(u) : "f"(f));
    return u;
}

__device__ __forceinline__ void mma_tf32(float c[4], const unsigned a[4], const unsigned b[2]) {
    asm("mma.sync.aligned.m16n8k8.row.col.f32.tf32.tf32.f32 "
        "{%0,%1,%2,%3}, {%4,%5,%6,%7}, {%8,%9}, {%0,%1,%2,%3};"
        : "+f"(c[0]), "+f"(c[1]), "+f"(c[2]), "+f"(c[3])
        : "r"(a[0]), "r"(a[1]), "r"(a[2]), "r"(a[3]), "r"(b[0]), "r"(b[1]));
}

// ---------------- one-kernel graph build: bucket scatter ------------------------
__global__ void k_fill(const int* __restrict__ ei32) {
    __shared__ int s_w64;
    if (threadIdx.x < 32) {
        int any = 0;
#pragma unroll
        for (int k = 0; k < 16; k++) any |= ei32[2 * (threadIdx.x + 32 * k) + 1];
        unsigned b = __ballot_sync(0xffffffffu, any != 0);
        if (threadIdx.x == 0) s_w64 = (b == 0) ? 1 : 0;
    }
    __syncthreads();
    const int w64 = s_w64;
    int i = blockIdx.x * blockDim.x + threadIdx.x;
    if (i < ET) {
        int src, dst;
        if (i < EE) {
            if (w64) {
                src = (int)((const long long*)ei32)[i];
                dst = (int)((const long long*)ei32)[EE + i];
            } else {
                src = ei32[i];
                dst = ei32[EE + i];
            }
        } else {
            src = dst = i - EE;  // self loop
        }
        int slot = atomicAdd(&g_cnt[dst * PAD], 1);
        g_csrc[dst * BUCKET + slot] = src;
    }
}

// ---------------- tf32 MMA GEMM1 + fused escore1 + fp16 output -----------------
__global__ void __launch_bounds__(256) k_mma1(const float* __restrict__ A,
                                              const float* __restrict__ B,
                                              const float* __restrict__ as1f,
                                              const float* __restrict__ ad1f) {
    __shared__ unsigned As[128][36];
    __shared__ unsigned Bs[32][136];
    __shared__ float s_e[128][2][2];   // [row][head_local][es/ed]
    const int bm = blockIdx.x * 128, bn = blockIdx.y * 128;
    const int tid = threadIdx.x;
    const int warp = tid >> 5, lane = tid & 31;
    const int wm = (warp & 1) * 64, wn = (warp >> 1) * 32;
    const int lq = lane >> 2, lr = lane & 3;
    float c[4][4][4] = {};

    {
        float* p = &s_e[0][0][0];
        p[tid] = 0.f; p[tid + 256] = 0.f;
    }

    for (int kc = 0; kc < 128; kc += 32) {
#pragma unroll
        for (int i = 0; i < 4; i++) {
            int idx = tid + i * 256;
            int row = idx >> 3, c4 = (idx & 7) * 4;
            int gr = bm + row;
            float4 v = (gr < NN) ? *(const float4*)(A + (size_t)gr * 128 + kc + c4)
                                 : make_float4(0.f, 0.f, 0.f, 0.f);
            As[row][c4 + 0] = f2tf32(v.x); As[row][c4 + 1] = f2tf32(v.y);
            As[row][c4 + 2] = f2tf32(v.z); As[row][c4 + 3] = f2tf32(v.w);
        }
#pragma unroll
        for (int i = 0; i < 4; i++) {
            int idx = tid + i * 256;
            int row = idx >> 5, c4 = (idx & 31) * 4;
            float4 v = *(const float4*)(B + (size_t)(kc + row) * F1 + bn + c4);
            Bs[row][c4 + 0] = f2tf32(v.x); Bs[row][c4 + 1] = f2tf32(v.y);
            Bs[row][c4 + 2] = f2tf32(v.z); Bs[row][c4 + 3] = f2tf32(v.w);
        }
        __syncthreads();
#pragma unroll
        for (int ks = 0; ks < 4; ks++) {
            unsigned a[4][4], b[4][2];
#pragma unroll
            for (int mt = 0; mt < 4; mt++) {
                int r0 = wm + mt * 16 + lq;
                a[mt][0] = As[r0][ks * 8 + lr];
                a[mt][1] = As[r0 + 8][ks * 8 + lr];
                a[mt][2] = As[r0][ks * 8 + lr + 4];
                a[mt][3] = As[r0 + 8][ks * 8 + lr + 4];
            }
#pragma unroll
            for (int nt = 0; nt < 4; nt++) {
                int cn = wn + nt * 8 + lq;
                b[nt][0] = Bs[ks * 8 + lr][cn];
                b[nt][1] = Bs[ks * 8 + lr + 4][cn];
            }
#pragma unroll
            for (int mt = 0; mt < 4; mt++)
#pragma unroll
                for (int nt = 0; nt < 4; nt++) mma_tf32(c[mt][nt], a[mt], b[nt]);
        }
        __syncthreads();
    }

    const int head_loc = wn >> 6;
    float ae[4][2], ad[4][2];
#pragma unroll
    for (int nt = 0; nt < 4; nt++) {
        int gc = bn + wn + nt * 8 + 2 * lr;
        ae[nt][0] = as1f[gc]; ae[nt][1] = as1f[gc + 1];
        ad[nt][0] = ad1f[gc]; ad[nt][1] = ad1f[gc + 1];
    }

#pragma unroll
    for (int mt = 0; mt < 4; mt++) {
        int row0 = bm + wm + mt * 16 + lq;
        float pe0 = 0.f, pd0 = 0.f, pe1 = 0.f, pd1 = 0.f;
#pragma unroll
        for (int nt = 0; nt < 4; nt++) {
            int col = bn + wn + nt * 8 + 2 * lr;
            if (row0 < NN)
                *(__half2*)(g_h1h + (size_t)row0 * F1 + col) =
                    __floats2half2_rn(c[mt][nt][0], c[mt][nt][1]);
            if (row0 + 8 < NN)
                *(__half2*)(g_h1h + (size_t)(row0 + 8) * F1 + col) =
                    __floats2half2_rn(c[mt][nt][2], c[mt][nt][3]);
            pe0 += c[mt][nt][0] * ae[nt][0] + c[mt][nt][1] * ae[nt][1];
            pd0 += c[mt][nt][0] * ad[nt][0] + c[mt][nt][1] * ad[nt][1];
            pe1 += c[mt][nt][2] * ae[nt][0] + c[mt][nt][3] * ae[nt][1];
            pd1 += c[mt][nt][2] * ad[nt][0] + c[mt][nt][3] * ad[nt][1];
        }
#pragma unroll
        for (int o = 1; o <= 2; o <<= 1) {
            pe0 += __shfl_xor_sync(0xffffffffu, pe0, o);
            pd0 += __shfl_xor_sync(0xffffffffu, pd0, o);
            pe1 += __shfl_xor_sync(0xffffffffu, pe1, o);
            pd1 += __shfl_xor_sync(0xffffffffu, pd1, o);
        }
        if (lr == 0) {
            int rl = wm + mt * 16 + lq;
            atomicAdd(&s_e[rl][head_loc][0], pe0);
            atomicAdd(&s_e[rl][head_loc][1], pd0);
            atomicAdd(&s_e[rl + 8][head_loc][0], pe1);
            atomicAdd(&s_e[rl + 8][head_loc][1], pd1);
        }
    }
    __syncthreads();
    {
        int row = tid >> 1, hh = tid & 1;
        int gr = bm + row;
        if (gr < NN) {
            int hg = (bn >> 6) + hh;
            g_es1[gr * 8 + hg] = s_e[row][hh][0];
            g_ed1[gr * 8 + hg] = s_e[row][hh][1];
        }
    }
}

// ---------------- tf32 MMA GEMM2 + fused escore2 (double-buffered) -------------
__global__ void __launch_bounds__(256) k_mma2(const float* __restrict__ B,
                                              const float* __restrict__ as2f,
                                              const float* __restrict__ ad2f) {
    __shared__ unsigned As[2][64][36];
    __shared__ unsigned Bs[2][32][72];
    __shared__ float s_e[64][2];
    const int bm = blockIdx.x * 64;
    const int tid = threadIdx.x;
    const int warp = tid >> 5, lane = tid & 31;
    const int wm = (warp & 1) * 32, wn = (warp >> 1) * 16;
    const int lq = lane >> 2, lr = lane & 3;
    float c[2][2][4] = {};

    if (tid < 128) (&s_e[0][0])[tid] = 0.f;

    const int arow = tid >> 3, ac4 = (tid & 7) * 4;
    const int brow = tid >> 4, bc4 = (tid & 15) * 4;
    float4 pa[2], pb[2];

    auto loadG = [&](int kc) {
#pragma unroll
        for (int i = 0; i < 2; i++) {
            int row = arow + i * 32;
            int gr = bm + row;
            pa[i] = (gr < NN) ? *(const float4*)(g_h1e + (size_t)gr * F1 + kc + ac4)
                              : make_float4(0.f, 0.f, 0.f, 0.f);
            int rowb = brow + i * 16;
            pb[i] = *(const float4*)(B + (size_t)(kc + rowb) * HID + bc4);
        }
    };
    auto storeS = [&](int buf) {
#pragma unroll
        for (int i = 0; i < 2; i++) {
            int row = arow + i * 32;
            As[buf][row][ac4 + 0] = f2tf32(pa[i].x); As[buf][row][ac4 + 1] = f2tf32(pa[i].y);
            As[buf][row][ac4 + 2] = f2tf32(pa[i].z); As[buf][row][ac4 + 3] = f2tf32(pa[i].w);
            int rowb = brow + i * 16;
            Bs[buf][rowb][bc4 + 0] = f2tf32(pb[i].x); Bs[buf][rowb][bc4 + 1] = f2tf32(pb[i].y);
            Bs[buf][rowb][bc4 + 2] = f2tf32(pb[i].z); Bs[buf][rowb][bc4 + 3] = f2tf32(pb[i].w);
        }
    };

    loadG(0);
    storeS(0);
    __syncthreads();

    int buf = 0;
    for (int kt = 0; kt < F1 / 32; kt++) {
        if (kt + 1 < F1 / 32) loadG((kt + 1) * 32);   // prefetch overlaps compute
#pragma unroll
        for (int ks = 0; ks < 4; ks++) {
            unsigned a[2][4], b[2][2];
#pragma unroll
            for (int mt = 0; mt < 2; mt++) {
                int r0 = wm + mt * 16 + lq;
                a[mt][0] = As[buf][r0][ks * 8 + lr];
                a[mt][1] = As[buf][r0 + 8][ks * 8 + lr];
                a[mt][2] = As[buf][r0][ks * 8 + lr + 4];
                a[mt][3] = As[buf][r0 + 8][ks * 8 + lr + 4];
            }
#pragma unroll
            for (int nt = 0; nt < 2; nt++) {
                int cn = wn + nt * 8 + lq;
                b[nt][0] = Bs[buf][ks * 8 + lr][cn];
                b[nt][1] = Bs[buf][ks * 8 + lr + 4][cn];
            }
#pragma unroll
            for (int mt = 0; mt < 2; mt++)
#pragma unroll
                for (int nt = 0; nt < 2; nt++) mma_tf32(c[mt][nt], a[mt], b[nt]);
        }
        if (kt + 1 < F1 / 32) {
            storeS(buf ^ 1);
            __syncthreads();
            buf ^= 1;
        }
    }

    float ae[2][2], ad[2][2];
#pragma unroll
    for (int nt = 0; nt < 2; nt++) {
        int gc = wn + nt * 8 + 2 * lr;
        ae[nt][0] = as2f[gc]; ae[nt][1] = as2f[gc + 1];
        ad[nt][0] = ad2f[gc]; ad[nt][1] = ad2f[gc + 1];
    }

#pragma unroll
    for (int mt = 0; mt < 2; mt++) {
        int row0 = bm + wm + mt * 16 + lq;
        float pe0 = 0.f, pd0 = 0.f, pe1 = 0.f, pd1 = 0.f;
#pragma unroll
        for (int nt = 0; nt < 2; nt++) {
            int col = wn + nt * 8 + 2 * lr;
            if (row0 < NN)
                *(float2*)(g_h2 + (size_t)row0 * HID + col) = make_float2(c[mt][nt][0], c[mt][nt][1]);
            if (row0 + 8 < NN)
                *(float2*)(g_h2 + (size_t)(row0 + 8) * HID + col) = make_float2(c[mt][nt][2], c[mt][nt][3]);
            pe0 += c[mt][nt][0] * ae[nt][0] + c[mt][nt][1] * ae[nt][1];
            pd0 += c[mt][nt][0] * ad[nt][0] + c[mt][nt][1] * ad[nt][1];
            pe1 += c[mt][nt][2] * ae[nt][0] + c[mt][nt][3] * ae[nt][1];
            pd1 += c[mt][nt][2] * ad[nt][0] + c[mt][nt][3] * ad[nt][1];
        }
#pragma unroll
        for (int o = 1; o <= 2; o <<= 1) {
            pe0 += __shfl_xor_sync(0xffffffffu, pe0, o);
            pd0 += __shfl_xor_sync(0xffffffffu, pd0, o);
            pe1 += __shfl_xor_sync(0xffffffffu, pe1, o);
            pd1 += __shfl_xor_sync(0xffffffffu, pd1, o);
        }
        if (lr == 0) {
            int rl = wm + mt * 16 + lq;
            atomicAdd(&s_e[rl][0], pe0);
            atomicAdd(&s_e[rl][1], pd0);
            atomicAdd(&s_e[rl + 8][0], pe1);
            atomicAdd(&s_e[rl + 8][1], pd1);
        }
    }
    __syncthreads();
    if (tid < 64) {
        int gr = bm + tid;
        if (gr < NN) {
            g_es2[gr] = s_e[tid][0];
            g_ed2[gr] = s_e[tid][1];
        }
    }
}

// ------- layer 1: softmax + fp16 gather (2-way edge-parallel, prefetched) ------
__global__ void __launch_bounds__(128) k_gat1(const float* __restrict__ b1) {
    const int d = blockIdx.x, tid = threadIdx.x;
    const int lane = tid & 31, warp = tid >> 5;
    const int off = d * BUCKET;
    const int deg = g_cnt[d * PAD];
    __shared__ int s_src[64];
    __shared__ float s_w[64 * 8];
    __shared__ float s_den[8];
    __shared__ float s_red[64 * 8];
    if (tid < 8) s_den[tid] = 0.f;
    float edh[8];
    *(float4*)edh       = *(const float4*)(g_ed1 + d * 8);
    *(float4*)(edh + 4) = *(const float4*)(g_ed1 + d * 8 + 4);
    const int gid = tid >> 6;
    const int st  = tid & 63;
    const int h = st >> 3, c8 = st & 7;
    float acc[8] = {};

    for (int base = 0; base < deg; base += 64) {
        int n = min(64, deg - base);
        __syncthreads();
        if (tid < n) {
            int s = g_csrc[off + base + tid];
            s_src[tid] = s;
            float es[8];
            *(float4*)es       = *(const float4*)(g_es1 + s * 8);
            *(float4*)(es + 4) = *(const float4*)(g_es1 + s * 8 + 4);
#pragma unroll
            for (int hh = 0; hh < 8; hh++)
                s_w[tid * 8 + hh] = __expf(lrelu(es[hh] + edh[hh]));
        }
        __syncthreads();
#pragma unroll
        for (int q = 0; q < 2; q++) {
            int hh = 2 * warp + q;
            float t = (lane < n) ? s_w[lane * 8 + hh] : 0.f;
            if (lane + 32 < n) t += s_w[(lane + 32) * 8 + hh];
#pragma unroll
            for (int o = 16; o; o >>= 1) t += __shfl_xor_sync(0xffffffffu, t, o);
            if (lane == 0) s_den[hh] += t;
        }
        // weighted gather: group gid handles edges j = gid, gid+2, ...
        // software-pipelined: prefetch j+2's feature row and weight
        int j = gid;
        if (j < n) {
            float w_cur = s_w[j * 8 + h];
            uint4 u_cur = *(const uint4*)(g_h1h + (size_t)s_src[j] * F1 + h * HID + c8 * 8);
            while (true) {
                int jn = j + 2;
                float w_nxt = 0.f;
                uint4 u_nxt;
                bool more = (jn < n);
                if (more) {
                    w_nxt = s_w[jn * 8 + h];
                    u_nxt = *(const uint4*)(g_h1h + (size_t)s_src[jn] * F1 + h * HID + c8 * 8);
                }
                float2 f0 = __half22float2(*(__half2*)&u_cur.x);
                float2 f1 = __half22float2(*(__half2*)&u_cur.y);
                float2 f2 = __half22float2(*(__half2*)&u_cur.z);
                float2 f3 = __half22float2(*(__half2*)&u_cur.w);
                acc[0] += w_cur * f0.x; acc[1] += w_cur * f0.y;
                acc[2] += w_cur * f1.x; acc[3] += w_cur * f1.y;
                acc[4] += w_cur * f2.x; acc[5] += w_cur * f2.y;
                acc[6] += w_cur * f3.x; acc[7] += w_cur * f3.y;
                if (!more) break;
                w_cur = w_nxt; u_cur = u_nxt; j = jn;
            }
        }
    }
    __syncthreads();
    if (gid == 1) {
#pragma unroll
        for (int k = 0; k < 8; k++) s_red[st * 8 + k] = acc[k];
    }
    __syncthreads();
    if (gid == 0) {
#pragma unroll
        for (int k = 0; k < 8; k++) acc[k] += s_red[st * 8 + k];
        const float inv = 1.f / (s_den[h] + 1e-16f);
        const int cb = h * HID + c8 * 8;
        float o[8];
#pragma unroll
        for (int k = 0; k < 8; k++) {
            float v = acc[k] * inv + b1[cb + k];
            o[k] = v > 0.f ? v : (__expf(v) - 1.f);   // ELU
        }
        *(float4*)(g_h1e + (size_t)d * F1 + cb)     = make_float4(o[0], o[1], o[2], o[3]);
        *(float4*)(g_h1e + (size_t)d * F1 + cb + 4) = make_float4(o[4], o[5], o[6], o[7]);
    }
}

// ---------------- layer 2 (+ fused classifier, + counter self-clean) -----------
__global__ void __launch_bounds__(128) k_gat2(const float* __restrict__ b2,
                                              const float* __restrict__ Wc,
                                              const float* __restrict__ bcp,
                                              float* __restrict__ out) {
    const int d = blockIdx.x, tid = threadIdx.x;
    const int lane = tid & 31, warp = tid >> 5;
    const int off = d * BUCKET;
    const int deg = g_cnt[d * PAD];
    __shared__ int s_src[64];
    __shared__ float s_w[64];
    __shared__ float s_den;
    __shared__ float s_acc[8][64];
    __shared__ float s_out[64];
    if (tid == 0) s_den = 0.f;
    const float edv = g_ed2[d];
    const int el = tid >> 4, c4 = tid & 15;
    float4 acc = make_float4(0.f, 0.f, 0.f, 0.f);

    for (int base = 0; base < deg; base += 64) {
        int n = min(64, deg - base);
        __syncthreads();
        if (tid < n) {
            int s = g_csrc[off + base + tid];
            s_src[tid] = s;
            s_w[tid] = __expf(lrelu(g_es2[s] + edv));
        }
        __syncthreads();
        if (warp == 0) {
            float t = (lane < n) ? s_w[lane] : 0.f;
            if (lane + 32 < n) t += s_w[lane + 32];
#pragma unroll
            for (int o = 16; o; o >>= 1) t += __shfl_xor_sync(0xffffffffu, t, o);
            if (lane == 0) s_den += t;
        }
        // prefetched j-loop (stride 8)
        int j = el;
        if (j < n) {
            float w_cur = s_w[j];
            float4 v_cur = *(const float4*)(g_h2 + (size_t)s_src[j] * HID + c4 * 4);
            while (true) {
                int jn = j + 8;
                float w_nxt = 0.f;
                float4 v_nxt;
                bool more = (jn < n);
                if (more) {
                    w_nxt = s_w[jn];
                    v_nxt = *(const float4*)(g_h2 + (size_t)s_src[jn] * HID + c4 * 4);
                }
                acc.x += w_cur * v_cur.x; acc.y += w_cur * v_cur.y;
                acc.z += w_cur * v_cur.z; acc.w += w_cur * v_cur.w;
                if (!more) break;
                w_cur = w_nxt; v_cur = v_nxt; j = jn;
            }
        }
    }
    s_acc[el][c4 * 4 + 0] = acc.x;
    s_acc[el][c4 * 4 + 1] = acc.y;
    s_acc[el][c4 * 4 + 2] = acc.z;
    s_acc[el][c4 * 4 + 3] = acc.w;
    __syncthreads();
    if (tid < 64) {
        float v = 0.f;
#pragma unroll
        for (int e = 0; e < 8; e++) v += s_acc[e][tid];
        s_out[tid] = v / (s_den + 1e-16f) + b2[tid];
    }
    __syncthreads();
    if (tid < 2) {
        float r = bcp[tid];
#pragma unroll
        for (int c = 0; c < 64; c++) r += s_out[c] * Wc[c * 2 + tid];
        out[d * 2 + tid] = r;
    }
    if (tid == 64) g_cnt[d * PAD] = 0;   // self-clean for next invocation
}

// ---------------- launch --------------------------------------------------------
extern "C" void kernel_launch(void* const* d_in, const int* in_sizes, int n_in,
                              void* d_out, int out_size) {
    const float* x   = (const float*)d_in[0];
    const int*   ei  = (const int*)d_in[1];
    const float* W1  = (const float*)d_in[2];
    const float* as1 = (const float*)d_in[3];
    const float* ad1 = (const float*)d_in[4];
    const float* b1  = (const float*)d_in[5];
    const float* W2  = (const float*)d_in[6];
    const float* as2 = (const float*)d_in[7];
    const float* ad2 = (const float*)d_in[8];
    const float* b2  = (const float*)d_in[9];
    const float* Wc  = (const float*)d_in[10];
    const float* bc  = (const float*)d_in[11];
    float* out = (float*)d_out;

    cudaStream_t sB;
    cudaEvent_t evF, evJ;
    cudaStreamCreateWithFlags(&sB, cudaStreamNonBlocking);
    cudaEventCreateWithFlags(&evF, cudaEventDisableTiming);
    cudaEventCreateWithFlags(&evJ, cudaEventDisableTiming);

    // fork: mma1 on side stream, graph build on main stream
    cudaEventRecord(evF, 0);
    cudaStreamWaitEvent(sB, evF, 0);
    {
        dim3 g((NN + 127) / 128, F1 / 128), b(256);
        k_mma1<<<g, b, 0, sB>>>(x, W1, as1, ad1);
    }
    cudaEventRecord(evJ, sB);

    k_fill<<<(ET + 255) / 256, 256>>>(ei);

    // join: gat1 needs both graph and mma1 output
    cudaStreamWaitEvent(0, evJ, 0);
    k_gat1<<<NN, 128>>>(b1);

    // layer 2
    k_mma2<<<(NN + 63) / 64, 256>>>(W2, as2, ad2);
    k_gat2<<<NN, 128>>>(b2, Wc, bc, out);
}

// round 17
// speedup vs baseline: 1.0827x; 1.0827x over previous
#include <cuda_runtime.h>
#include <cuda_fp16.h>

#define NN 10000
#define EE 320000
#define ET (EE + NN)
#define F1 512    // HEADS*HID
#define HID 64
#define HEADS 8
#define PAD 32    // 128B stride for atomic counters (LTS spread)
#define BUCKET 128 // fixed per-node edge capacity (max deg ~57 « 128)
#define WS 9      // padded stride for gat1 weight table (conflict-free)

// ---------------- scratch (static device memory; no allocations) -------------
__device__ __half g_h1h[NN * F1];    // fp16 h1 (written by mma1 epilogue)
__device__ float  g_h1e[NN * F1];    // layer-1 output after bias+ELU
__device__ float  g_h2[NN * HID];    // h1e @ W2
__device__ float  g_es1[NN * HEADS];
__device__ float  g_ed1[NN * HEADS];
__device__ float  g_es2[NN];
__device__ float  g_ed2[NN];
__device__ int    g_cnt[NN * PAD];   // per-node degree counters (zero-init; self-cleaned by k_gat2)
__device__ int    g_csrc[NN * BUCKET];

__device__ __forceinline__ float lrelu(float e) { return e > 0.f ? e : 0.2f * e; }

__device__ __forceinline__ unsigned f2tf32(float f) {
    unsigned u;
    asm("cvt.rna.tf32.f32 %0, %1;" : "=r"(u) : "f"(f));
    return u;
}

__device__ __forceinline__ void mma_tf32(float c[4], const unsigned a[4], const unsigned b[2]) {
    asm("mma.sync.aligned.m16n8k8.row.col.f32.tf32.tf32.f32 "
        "{%0,%1,%2,%3}, {%4,%5,%6,%7}, {%8,%9}, {%0,%1,%2,%3};"
        : "+f"(c[0]), "+f"(c[1]), "+f"(c[2]), "+f"(c[3])
        : "r"(a[0]), "r"(a[1]), "r"(a[2]), "r"(a[3]), "r"(b[0]), "r"(b[1]));
}

// ---------------- one-kernel graph build: bucket scatter ------------------------
__global__ void k_fill(const int* __restrict__ ei32) {
    __shared__ int s_w64;
    if (threadIdx.x < 32) {
        int any = 0;
#pragma unroll
        for (int k = 0; k < 16; k++) any |= ei32[2 * (threadIdx.x + 32 * k) + 1];
        unsigned b = __ballot_sync(0xffffffffu, any != 0);
        if (threadIdx.x == 0) s_w64 = (b == 0) ? 1 : 0;
    }
    __syncthreads();
    const int w64 = s_w64;
    int i = blockIdx.x * blockDim.x + threadIdx.x;
    if (i < ET) {
        int src, dst;
        if (i < EE) {
            if (w64) {
                src = (int)((const long long*)ei32)[i];
                dst = (int)((const long long*)ei32)[EE + i];
            } else {
                src = ei32[i];
                dst = ei32[EE + i];
            }
        } else {
            src = dst = i - EE;  // self loop
        }
        int slot = atomicAdd(&g_cnt[dst * PAD], 1);
        g_csrc[dst * BUCKET + slot] = src;
    }
}

// ---------------- tf32 MMA GEMM1 + fused escore1 + fp16 output -----------------
__global__ void __launch_bounds__(256) k_mma1(const float* __restrict__ A,
                                              const float* __restrict__ B,
                                              const float* __restrict__ as1f,
                                              const float* __restrict__ ad1f) {
    __shared__ unsigned As[128][36];
    __shared__ unsigned Bs[32][136];
    __shared__ float s_e[128][2][2];   // [row][head_local][es/ed]
    const int bm = blockIdx.x * 128, bn = blockIdx.y * 128;
    const int tid = threadIdx.x;
    const int warp = tid >> 5, lane = tid & 31;
    const int wm = (warp & 1) * 64, wn = (warp >> 1) * 32;
    const int lq = lane >> 2, lr = lane & 3;
    float c[4][4][4] = {};

    {
        float* p = &s_e[0][0][0];
        p[tid] = 0.f; p[tid + 256] = 0.f;
    }

    for (int kc = 0; kc < 128; kc += 32) {
#pragma unroll
        for (int i = 0; i < 4; i++) {
            int idx = tid + i * 256;
            int row = idx >> 3, c4 = (idx & 7) * 4;
            int gr = bm + row;
            float4 v = (gr < NN) ? *(const float4*)(A + (size_t)gr * 128 + kc + c4)
                                 : make_float4(0.f, 0.f, 0.f, 0.f);
            As[row][c4 + 0] = f2tf32(v.x); As[row][c4 + 1] = f2tf32(v.y);
            As[row][c4 + 2] = f2tf32(v.z); As[row][c4 + 3] = f2tf32(v.w);
        }
#pragma unroll
        for (int i = 0; i < 4; i++) {
            int idx = tid + i * 256;
            int row = idx >> 5, c4 = (idx & 31) * 4;
            float4 v = *(const float4*)(B + (size_t)(kc + row) * F1 + bn + c4);
            Bs[row][c4 + 0] = f2tf32(v.x); Bs[row][c4 + 1] = f2tf32(v.y);
            Bs[row][c4 + 2] = f2tf32(v.z); Bs[row][c4 + 3] = f2tf32(v.w);
        }
        __syncthreads();
#pragma unroll
        for (int ks = 0; ks < 4; ks++) {
            unsigned a[4][4], b[4][2];
#pragma unroll
            for (int mt = 0; mt < 4; mt++) {
                int r0 = wm + mt * 16 + lq;
                a[mt][0] = As[r0][ks * 8 + lr];
                a[mt][1] = As[r0 + 8][ks * 8 + lr];
                a[mt][2] = As[r0][ks * 8 + lr + 4];
                a[mt][3] = As[r0 + 8][ks * 8 + lr + 4];
            }
#pragma unroll
            for (int nt = 0; nt < 4; nt++) {
                int cn = wn + nt * 8 + lq;
                b[nt][0] = Bs[ks * 8 + lr][cn];
                b[nt][1] = Bs[ks * 8 + lr + 4][cn];
            }
#pragma unroll
            for (int mt = 0; mt < 4; mt++)
#pragma unroll
                for (int nt = 0; nt < 4; nt++) mma_tf32(c[mt][nt], a[mt], b[nt]);
        }
        __syncthreads();
    }

    const int head_loc = wn >> 6;
    float ae[4][2], ad[4][2];
#pragma unroll
    for (int nt = 0; nt < 4; nt++) {
        int gc = bn + wn + nt * 8 + 2 * lr;
        ae[nt][0] = as1f[gc]; ae[nt][1] = as1f[gc + 1];
        ad[nt][0] = ad1f[gc]; ad[nt][1] = ad1f[gc + 1];
    }

#pragma unroll
    for (int mt = 0; mt < 4; mt++) {
        int row0 = bm + wm + mt * 16 + lq;
        float pe0 = 0.f, pd0 = 0.f, pe1 = 0.f, pd1 = 0.f;
#pragma unroll
        for (int nt = 0; nt < 4; nt++) {
            int col = bn + wn + nt * 8 + 2 * lr;
            if (row0 < NN)
                *(__half2*)(g_h1h + (size_t)row0 * F1 + col) =
                    __floats2half2_rn(c[mt][nt][0], c[mt][nt][1]);
            if (row0 + 8 < NN)
                *(__half2*)(g_h1h + (size_t)(row0 + 8) * F1 + col) =
                    __floats2half2_rn(c[mt][nt][2], c[mt][nt][3]);
            pe0 += c[mt][nt][0] * ae[nt][0] + c[mt][nt][1] * ae[nt][1];
            pd0 += c[mt][nt][0] * ad[nt][0] + c[mt][nt][1] * ad[nt][1];
            pe1 += c[mt][nt][2] * ae[nt][0] + c[mt][nt][3] * ae[nt][1];
            pd1 += c[mt][nt][2] * ad[nt][0] + c[mt][nt][3] * ad[nt][1];
        }
#pragma unroll
        for (int o = 1; o <= 2; o <<= 1) {
            pe0 += __shfl_xor_sync(0xffffffffu, pe0, o);
            pd0 += __shfl_xor_sync(0xffffffffu, pd0, o);
            pe1 += __shfl_xor_sync(0xffffffffu, pe1, o);
            pd1 += __shfl_xor_sync(0xffffffffu, pd1, o);
        }
        if (lr == 0) {
            int rl = wm + mt * 16 + lq;
            atomicAdd(&s_e[rl][head_loc][0], pe0);
            atomicAdd(&s_e[rl][head_loc][1], pd0);
            atomicAdd(&s_e[rl + 8][head_loc][0], pe1);
            atomicAdd(&s_e[rl + 8][head_loc][1], pd1);
        }
    }
    __syncthreads();
    {
        int row = tid >> 1, hh = tid & 1;
        int gr = bm + row;
        if (gr < NN) {
            int hg = (bn >> 6) + hh;
            g_es1[gr * 8 + hg] = s_e[row][hh][0];
            g_ed1[gr * 8 + hg] = s_e[row][hh][1];
        }
    }
}

// ---------------- tf32 MMA GEMM2 + fused escore2 (double-buffered) -------------
__global__ void __launch_bounds__(256) k_mma2(const float* __restrict__ B,
                                              const float* __restrict__ as2f,
                                              const float* __restrict__ ad2f) {
    __shared__ unsigned As[2][64][36];
    __shared__ unsigned Bs[2][32][72];
    __shared__ float s_e[64][2];
    const int bm = blockIdx.x * 64;
    const int tid = threadIdx.x;
    const int warp = tid >> 5, lane = tid & 31;
    const int wm = (warp & 1) * 32, wn = (warp >> 1) * 16;
    const int lq = lane >> 2, lr = lane & 3;
    float c[2][2][4] = {};

    if (tid < 128) (&s_e[0][0])[tid] = 0.f;

    const int arow = tid >> 3, ac4 = (tid & 7) * 4;
    const int brow = tid >> 4, bc4 = (tid & 15) * 4;
    float4 pa[2], pb[2];

    auto loadG = [&](int kc) {
#pragma unroll
        for (int i = 0; i < 2; i++) {
            int row = arow + i * 32;
            int gr = bm + row;
            pa[i] = (gr < NN) ? *(const float4*)(g_h1e + (size_t)gr * F1 + kc + ac4)
                              : make_float4(0.f, 0.f, 0.f, 0.f);
            int rowb = brow + i * 16;
            pb[i] = *(const float4*)(B + (size_t)(kc + rowb) * HID + bc4);
        }
    };
    auto storeS = [&](int buf) {
#pragma unroll
        for (int i = 0; i < 2; i++) {
            int row = arow + i * 32;
            As[buf][row][ac4 + 0] = f2tf32(pa[i].x); As[buf][row][ac4 + 1] = f2tf32(pa[i].y);
            As[buf][row][ac4 + 2] = f2tf32(pa[i].z); As[buf][row][ac4 + 3] = f2tf32(pa[i].w);
            int rowb = brow + i * 16;
            Bs[buf][rowb][bc4 + 0] = f2tf32(pb[i].x); Bs[buf][rowb][bc4 + 1] = f2tf32(pb[i].y);
            Bs[buf][rowb][bc4 + 2] = f2tf32(pb[i].z); Bs[buf][rowb][bc4 + 3] = f2tf32(pb[i].w);
        }
    };

    loadG(0);
    storeS(0);
    __syncthreads();

    int buf = 0;
    for (int kt = 0; kt < F1 / 32; kt++) {
        if (kt + 1 < F1 / 32) loadG((kt + 1) * 32);   // prefetch overlaps compute
#pragma unroll
        for (int ks = 0; ks < 4; ks++) {
            unsigned a[2][4], b[2][2];
#pragma unroll
            for (int mt = 0; mt < 2; mt++) {
                int r0 = wm + mt * 16 + lq;
                a[mt][0] = As[buf][r0][ks * 8 + lr];
                a[mt][1] = As[buf][r0 + 8][ks * 8 + lr];
                a[mt][2] = As[buf][r0][ks * 8 + lr + 4];
                a[mt][3] = As[buf][r0 + 8][ks * 8 + lr + 4];
            }
#pragma unroll
            for (int nt = 0; nt < 2; nt++) {
                int cn = wn + nt * 8 + lq;
                b[nt][0] = Bs[buf][ks * 8 + lr][cn];
                b[nt][1] = Bs[buf][ks * 8 + lr + 4][cn];
            }
#pragma unroll
            for (int mt = 0; mt < 2; mt++)
#pragma unroll
                for (int nt = 0; nt < 2; nt++) mma_tf32(c[mt][nt], a[mt], b[nt]);
        }
        if (kt + 1 < F1 / 32) {
            storeS(buf ^ 1);
            __syncthreads();
            buf ^= 1;
        }
    }

    float ae[2][2], ad[2][2];
#pragma unroll
    for (int nt = 0; nt < 2; nt++) {
        int gc = wn + nt * 8 + 2 * lr;
        ae[nt][0] = as2f[gc]; ae[nt][1] = as2f[gc + 1];
        ad[nt][0] = ad2f[gc]; ad[nt][1] = ad2f[gc + 1];
    }

#pragma unroll
    for (int mt = 0; mt < 2; mt++) {
        int row0 = bm + wm + mt * 16 + lq;
        float pe0 = 0.f, pd0 = 0.f, pe1 = 0.f, pd1 = 0.f;
#pragma unroll
        for (int nt = 0; nt < 2; nt++) {
            int col = wn + nt * 8 + 2 * lr;
            if (row0 < NN)
                *(float2*)(g_h2 + (size_t)row0 * HID + col) = make_float2(c[mt][nt][0], c[mt][nt][1]);
            if (row0 + 8 < NN)
                *(float2*)(g_h2 + (size_t)(row0 + 8) * HID + col) = make_float2(c[mt][nt][2], c[mt][nt][3]);
            pe0 += c[mt][nt][0] * ae[nt][0] + c[mt][nt][1] * ae[nt][1];
            pd0 += c[mt][nt][0] * ad[nt][0] + c[mt][nt][1] * ad[nt][1];
            pe1 += c[mt][nt][2] * ae[nt][0] + c[mt][nt][3] * ae[nt][1];
            pd1 += c[mt][nt][2] * ad[nt][0] + c[mt][nt][3] * ad[nt][1];
        }
#pragma unroll
        for (int o = 1; o <= 2; o <<= 1) {
            pe0 += __shfl_xor_sync(0xffffffffu, pe0, o);
            pd0 += __shfl_xor_sync(0xffffffffu, pd0, o);
            pe1 += __shfl_xor_sync(0xffffffffu, pe1, o);
            pd1 += __shfl_xor_sync(0xffffffffu, pd1, o);
        }
        if (lr == 0) {
            int rl = wm + mt * 16 + lq;
            atomicAdd(&s_e[rl][0], pe0);
            atomicAdd(&s_e[rl][1], pd0);
            atomicAdd(&s_e[rl + 8][0], pe1);
            atomicAdd(&s_e[rl + 8][1], pd1);
        }
    }
    __syncthreads();
    if (tid < 64) {
        int gr = bm + tid;
        if (gr < NN) {
            g_es2[gr] = s_e[tid][0];
            g_ed2[gr] = s_e[tid][1];
        }
    }
}

// ---------------- layer 1: softmax + fp16 gather (2-way edge-parallel, 16B) ----
__global__ void __launch_bounds__(128) k_gat1(const float* __restrict__ b1) {
    const int d = blockIdx.x, tid = threadIdx.x;
    const int lane = tid & 31, warp = tid >> 5;
    const int off = d * BUCKET;
    const int deg = g_cnt[d * PAD];
    __shared__ int s_src[64];
    __shared__ float s_w[64 * WS];   // stride 9: conflict-free writes & reduction reads
    __shared__ float s_den[8];
    __shared__ float s_red[64 * 8];
    if (tid < 8) s_den[tid] = 0.f;
    float edh[8];
    *(float4*)edh       = *(const float4*)(g_ed1 + d * 8);
    *(float4*)(edh + 4) = *(const float4*)(g_ed1 + d * 8 + 4);
    const int gid = tid >> 6;         // edge-parity group
    const int st  = tid & 63;
    const int h = st >> 3, c8 = st & 7;  // head, 8-half chunk
    float acc[8] = {};

    for (int base = 0; base < deg; base += 64) {
        int n = min(64, deg - base);
        __syncthreads();
        if (tid < n) {
            int s = g_csrc[off + base + tid];
            s_src[tid] = s;
            float es[8];
            *(float4*)es       = *(const float4*)(g_es1 + s * 8);
            *(float4*)(es + 4) = *(const float4*)(g_es1 + s * 8 + 4);
#pragma unroll
            for (int hh = 0; hh < 8; hh++)
                s_w[tid * WS + hh] = __expf(lrelu(es[hh] + edh[hh]));
        }
        __syncthreads();
#pragma unroll
        for (int q = 0; q < 2; q++) {
            int hh = 2 * warp + q;
            float t = (lane < n) ? s_w[lane * WS + hh] : 0.f;
            if (lane + 32 < n) t += s_w[(lane + 32) * WS + hh];
#pragma unroll
            for (int o = 16; o; o >>= 1) t += __shfl_xor_sync(0xffffffffu, t, o);
            if (lane == 0) s_den[hh] += t;
        }
#pragma unroll 2
        for (int j = gid; j < n; j += 2) {
            float w = s_w[j * WS + h];
            const __half* hp = g_h1h + (size_t)s_src[j] * F1 + h * HID + c8 * 8;
            uint4 u = *(const uint4*)hp;
            float2 f0 = __half22float2(*(__half2*)&u.x);
            float2 f1 = __half22float2(*(__half2*)&u.y);
            float2 f2 = __half22float2(*(__half2*)&u.z);
            float2 f3 = __half22float2(*(__half2*)&u.w);
            acc[0] += w * f0.x; acc[1] += w * f0.y;
            acc[2] += w * f1.x; acc[3] += w * f1.y;
            acc[4] += w * f2.x; acc[5] += w * f2.y;
            acc[6] += w * f3.x; acc[7] += w * f3.y;
        }
    }
    __syncthreads();
    if (gid == 1) {
#pragma unroll
        for (int k = 0; k < 8; k++) s_red[st * 8 + k] = acc[k];
    }
    __syncthreads();
    if (gid == 0) {
#pragma unroll
        for (int k = 0; k < 8; k++) acc[k] += s_red[st * 8 + k];
        const float inv = 1.f / (s_den[h] + 1e-16f);
        const int cb = h * HID + c8 * 8;
        float o[8];
#pragma unroll
        for (int k = 0; k < 8; k++) {
            float v = acc[k] * inv + b1[cb + k];
            o[k] = v > 0.f ? v : (__expf(v) - 1.f);   // ELU
        }
        *(float4*)(g_h1e + (size_t)d * F1 + cb)     = make_float4(o[0], o[1], o[2], o[3]);
        *(float4*)(g_h1e + (size_t)d * F1 + cb + 4) = make_float4(o[4], o[5], o[6], o[7]);
    }
}

// ---------------- layer 2 (+ fused classifier, + counter self-clean) -----------
__global__ void __launch_bounds__(128) k_gat2(const float* __restrict__ b2,
                                              const float* __restrict__ Wc,
                                              const float* __restrict__ bcp,
                                              float* __restrict__ out) {
    const int d = blockIdx.x, tid = threadIdx.x;
    const int lane = tid & 31, warp = tid >> 5;
    const int off = d * BUCKET;
    const int deg = g_cnt[d * PAD];
    __shared__ int s_src[64];
    __shared__ float s_w[64];
    __shared__ float s_den;
    __shared__ float s_acc[8][64];
    __shared__ float s_out[64];
    if (tid == 0) s_den = 0.f;
    const float edv = g_ed2[d];
    const int el = tid >> 4, c4 = tid & 15;
    float4 acc = make_float4(0.f, 0.f, 0.f, 0.f);

    for (int base = 0; base < deg; base += 64) {
        int n = min(64, deg - base);
        __syncthreads();
        if (tid < n) {
            int s = g_csrc[off + base + tid];
            s_src[tid] = s;
            s_w[tid] = __expf(lrelu(g_es2[s] + edv));
        }
        __syncthreads();
        if (warp == 0) {
            float t = (lane < n) ? s_w[lane] : 0.f;
            if (lane + 32 < n) t += s_w[lane + 32];
#pragma unroll
            for (int o = 16; o; o >>= 1) t += __shfl_xor_sync(0xffffffffu, t, o);
            if (lane == 0) s_den += t;
        }
        for (int j = el; j < n; j += 8) {
            float w = s_w[j];
            const float4 v = *(const float4*)(g_h2 + (size_t)s_src[j] * HID + c4 * 4);
            acc.x += w * v.x; acc.y += w * v.y; acc.z += w * v.z; acc.w += w * v.w;
        }
    }
    s_acc[el][c4 * 4 + 0] = acc.x;
    s_acc[el][c4 * 4 + 1] = acc.y;
    s_acc[el][c4 * 4 + 2] = acc.z;
    s_acc[el][c4 * 4 + 3] = acc.w;
    __syncthreads();
    if (tid < 64) {
        float v = 0.f;
#pragma unroll
        for (int e = 0; e < 8; e++) v += s_acc[e][tid];
        s_out[tid] = v / (s_den + 1e-16f) + b2[tid];
    }
    __syncthreads();
    if (tid < 2) {
        float r = bcp[tid];
#pragma unroll
        for (int c = 0; c < 64; c++) r += s_out[c] * Wc[c * 2 + tid];
        out[d * 2 + tid] = r;
    }
    if (tid == 64) g_cnt[d * PAD] = 0;   // self-clean for next invocation
}

// ---------------- launch --------------------------------------------------------
extern "C" void kernel_launch(void* const* d_in, const int* in_sizes, int n_in,
                              void* d_out, int out_size) {
    const float* x   = (const float*)d_in[0];
    const int*   ei  = (const int*)d_in[1];
    const float* W1  = (const float*)d_in[2];
    const float* as1 = (const float*)d_in[3];
    const float* ad1 = (const float*)d_in[4];
    const float* b1  = (const float*)d_in[5];
    const float* W2  = (const float*)d_in[6];
    const float* as2 = (const float*)d_in[7];
    const float* ad2 = (const float*)d_in[8];
    const float* b2  = (const float*)d_in[9];
    const float* Wc  = (const float*)d_in[10];
    const float* bc  = (const float*)d_in[11];
    float* out = (float*)d_out;

    cudaStream_t sB;
    cudaEvent_t evF, evJ;
    cudaStreamCreateWithFlags(&sB, cudaStreamNonBlocking);
    cudaEventCreateWithFlags(&evF, cudaEventDisableTiming);
    cudaEventCreateWithFlags(&evJ, cudaEventDisableTiming);

    // fork: mma1 on side stream, graph build on main stream
    cudaEventRecord(evF, 0);
    cudaStreamWaitEvent(sB, evF, 0);
    {
        dim3 g((NN + 127) / 128, F1 / 128), b(256);
        k_mma1<<<g, b, 0, sB>>>(x, W1, as1, ad1);
    }
    cudaEventRecord(evJ, sB);

    k_fill<<<(ET + 255) / 256, 256>>>(ei);

    // join: gat1 needs both graph and mma1 output
    cudaStreamWaitEvent(0, evJ, 0);
    k_gat1<<<NN, 128>>>(b1);

    // layer 2
    k_mma2<<<(NN + 63) / 64, 256>>>(W2, as2, ad2);
    k_gat2<<<NN, 128>>>(b2, Wc, bc, out);
}